// round 2
// baseline (speedup 1.0000x reference)
#include <cuda_runtime.h>
#include <math.h>

// Problem constants (fixed by the dataset)
#define BB 128          // batch
#define HH 1024         // hidden
#define TT 512          // n_steps
#define NG (4*HH)       // 4096 combined gate columns (r, z, n_in, n_h)

// GEMM tiling
#define BM 64
#define BN 32           // 32 gate cols = 8 h-columns (j) per block
#define BK 16

// ---------------------------------------------------------------------------
// Device scratch (allowed: __device__ globals, no runtime allocation)
// ---------------------------------------------------------------------------
__device__ float g_Wci [NG * HH];        // steady combined weights, interleaved (j*4+g, k)   16.8 MB
__device__ float g_Wc0i[NG * 2 * HH];    // step-0 combined weights over K=2048               33.6 MB
__device__ float g_bci [NG];             // combined biases, interleaved
__device__ float g_a0  [BB * 2 * HH];    // [x0 | h0] concatenated input for step 0

// ---------------------------------------------------------------------------
// f32x2 packed math helpers (Blackwell)
// ---------------------------------------------------------------------------
__device__ __forceinline__ unsigned long long pack_dup(float v) {
    unsigned long long r;
    asm("mov.b64 %0, {%1, %1};" : "=l"(r) : "f"(v));
    return r;
}
__device__ __forceinline__ void ffma2(unsigned long long& d,
                                      unsigned long long a,
                                      unsigned long long b) {
    asm("fma.rn.f32x2 %0, %1, %2, %0;" : "+l"(d) : "l"(a), "l"(b));
}
__device__ __forceinline__ void unpack2(unsigned long long v, float& lo, float& hi) {
    asm("mov.b64 {%0, %1}, %2;" : "=f"(lo), "=f"(hi) : "l"(v));
}

// ---------------------------------------------------------------------------
// Prep kernels (run inside the graph every replay; deterministic)
// ---------------------------------------------------------------------------
__global__ void k_prep_wc(const float* __restrict__ Wih, const float* __restrict__ Whh) {
    int idx = blockIdx.x * blockDim.x + threadIdx.x;
    if (idx >= NG * HH) return;
    int k = idx & (HH - 1);
    int g = (idx >> 10) & 3;
    int j = idx >> 12;
    float v;
    if      (g == 0) v = Wih[j*HH + k]          + Whh[j*HH + k];
    else if (g == 1) v = Wih[(HH + j)*HH + k]   + Whh[(HH + j)*HH + k];
    else if (g == 2) v = Wih[(2*HH + j)*HH + k];
    else             v = Whh[(2*HH + j)*HH + k];
    g_Wci[idx] = v;
}

__global__ void k_prep_wc0(const float* __restrict__ Wih, const float* __restrict__ Whh) {
    int idx = blockIdx.x * blockDim.x + threadIdx.x;
    if (idx >= NG * 2 * HH) return;
    int k = idx & (2*HH - 1);
    int g = (idx >> 11) & 3;
    int j = idx >> 13;
    float v;
    if (k < HH) {
        if      (g == 0) v = Wih[j*HH + k];
        else if (g == 1) v = Wih[(HH + j)*HH + k];
        else if (g == 2) v = Wih[(2*HH + j)*HH + k];
        else             v = 0.0f;
    } else {
        int kk = k - HH;
        if      (g == 0) v = Whh[j*HH + kk];
        else if (g == 1) v = Whh[(HH + j)*HH + kk];
        else if (g == 2) v = 0.0f;
        else             v = Whh[(2*HH + j)*HH + kk];
    }
    g_Wc0i[idx] = v;
}

__global__ void k_prep_misc(const float* __restrict__ bih, const float* __restrict__ bhh,
                            const float* __restrict__ x0,  const float* __restrict__ h0,
                            float* __restrict__ xs) {
    int idx = blockIdx.x * blockDim.x + threadIdx.x;
    // combined biases
    if (idx < NG) {
        int g = idx & 3;
        int j = idx >> 2;
        float v;
        if      (g == 0) v = bih[j]        + bhh[j];
        else if (g == 1) v = bih[HH + j]   + bhh[HH + j];
        else if (g == 2) v = bih[2*HH + j];
        else             v = bhh[2*HH + j];
        g_bci[idx] = v;
    }
    // A0 = [x0 | h0]
    if (idx < BB * 2 * HH) {
        int b = idx >> 11;
        int k = idx & (2*HH - 1);
        g_a0[idx] = (k < HH) ? x0[b*HH + k] : h0[b*HH + (k - HH)];
    }
    // xs[:, 0, :] = x0
    if (idx < BB * HH) {
        int b = idx >> 10;
        int j = idx & (HH - 1);
        xs[b * (TT*HH) + j] = x0[idx];
    }
}

__global__ void k_final(float* __restrict__ outbase) {
    int idx = blockIdx.x * blockDim.x + threadIdx.x;
    if (idx >= BB * HH) return;
    int b = idx >> 10;
    int j = idx & (HH - 1);
    outbase[(size_t)BB * TT * HH + idx] = outbase[b * (TT*HH) + (TT - 1) * HH + j];
}

// ---------------------------------------------------------------------------
// Fused GEMM + GRU-cell step kernel.
//   g(128 x 4096) = A(128 x K) @ W^T  (W interleaved gate-innermost)
//   then per (m, j): r=sig, z=sig, n=tanh(ni + r*nh), h_new = n + z*(h_prev - n)
// Template: K (1024 steady / 2048 step0), STEP0 selects device-global W/A.
// ---------------------------------------------------------------------------
template<int K, bool STEP0>
__global__ void __launch_bounds__(128)
gru_step_kernel(const float* __restrict__ Ain, int lda,
                const float* __restrict__ hprev, int ldh,
                float* __restrict__ out, int ldo)
{
    __shared__ __align__(16) float sA[2][BK][2*BM];  // A values duplicated (splat pairs)
    __shared__ __align__(16) float sW[2][BK][BN];

    const float* __restrict__ A = STEP0 ? g_a0   : Ain;
    const float* __restrict__ W = STEP0 ? g_Wc0i : g_Wci;
    const int LDA = STEP0 ? (2*HH) : lda;          // <-- R1 fix: step-0 used lda=0

    const int tid  = threadIdx.x;
    const int tx   = tid & 7;        // j within tile (0..7), gate cols n0 = tx*4
    const int ty   = tid >> 3;       // row group (0..15), rows ty*4..ty*4+3
    const int mblk = blockIdx.y * BM;
    const int nblk = blockIdx.x * BN;

    // loader mapping
    const int ra = tid >> 1;          // A tile row 0..63
    const int ka = (tid & 1) * 8;     // k offset 0 or 8
    const int rw = tid >> 2;          // W tile row 0..31
    const int kw = (tid & 3) * 4;     // k offset 0,4,8,12

    const float* Ap = A + (mblk + ra) * LDA + ka;
    const float* Wp = W + (nblk + rw) * K + kw;

    float4 av0 = *(const float4*)(Ap);
    float4 av1 = *(const float4*)(Ap + 4);
    float4 wv  = *(const float4*)(Wp);

    unsigned long long acc[4][2];
#pragma unroll
    for (int i = 0; i < 4; i++) { acc[i][0] = 0ull; acc[i][1] = 0ull; }

    // stage chunk 0
    *(unsigned long long*)&sA[0][ka+0][2*ra] = pack_dup(av0.x);
    *(unsigned long long*)&sA[0][ka+1][2*ra] = pack_dup(av0.y);
    *(unsigned long long*)&sA[0][ka+2][2*ra] = pack_dup(av0.z);
    *(unsigned long long*)&sA[0][ka+3][2*ra] = pack_dup(av0.w);
    *(unsigned long long*)&sA[0][ka+4][2*ra] = pack_dup(av1.x);
    *(unsigned long long*)&sA[0][ka+5][2*ra] = pack_dup(av1.y);
    *(unsigned long long*)&sA[0][ka+6][2*ra] = pack_dup(av1.z);
    *(unsigned long long*)&sA[0][ka+7][2*ra] = pack_dup(av1.w);
    sW[0][kw+0][rw] = wv.x;
    sW[0][kw+1][rw] = wv.y;
    sW[0][kw+2][rw] = wv.z;
    sW[0][kw+3][rw] = wv.w;
    __syncthreads();

    const int nChunks = K / BK;
    int buf = 0;
    for (int c = 0; c < nChunks; c++) {
        if (c + 1 < nChunks) {
            const float* Ap2 = Ap + (c + 1) * BK;
            av0 = *(const float4*)(Ap2);
            av1 = *(const float4*)(Ap2 + 4);
            wv  = *(const float4*)(Wp + (c + 1) * BK);
        }
#pragma unroll
        for (int kk = 0; kk < BK; kk++) {
            unsigned long long b0 = *(const unsigned long long*)&sW[buf][kk][tx*4];
            unsigned long long b1 = *(const unsigned long long*)&sW[buf][kk][tx*4 + 2];
#pragma unroll
            for (int i = 0; i < 4; i++) {
                unsigned long long a = *(const unsigned long long*)&sA[buf][kk][(ty*4 + i)*2];
                ffma2(acc[i][0], a, b0);
                ffma2(acc[i][1], a, b1);
            }
        }
        if (c + 1 < nChunks) {
            int nb = buf ^ 1;
            *(unsigned long long*)&sA[nb][ka+0][2*ra] = pack_dup(av0.x);
            *(unsigned long long*)&sA[nb][ka+1][2*ra] = pack_dup(av0.y);
            *(unsigned long long*)&sA[nb][ka+2][2*ra] = pack_dup(av0.z);
            *(unsigned long long*)&sA[nb][ka+3][2*ra] = pack_dup(av0.w);
            *(unsigned long long*)&sA[nb][ka+4][2*ra] = pack_dup(av1.x);
            *(unsigned long long*)&sA[nb][ka+5][2*ra] = pack_dup(av1.y);
            *(unsigned long long*)&sA[nb][ka+6][2*ra] = pack_dup(av1.z);
            *(unsigned long long*)&sA[nb][ka+7][2*ra] = pack_dup(av1.w);
            sW[nb][kw+0][rw] = wv.x;
            sW[nb][kw+1][rw] = wv.y;
            sW[nb][kw+2][rw] = wv.z;
            sW[nb][kw+3][rw] = wv.w;
        }
        __syncthreads();
        buf ^= 1;
    }

    // Fused GRU cell epilogue. Thread owns the 4 gates of column j for 4 rows.
    const int j = (nblk >> 2) + tx;                    // h column 0..1023
    const float4 bj = *(const float4*)(g_bci + nblk + tx*4);
#pragma unroll
    for (int i = 0; i < 4; i++) {
        const int m = mblk + ty*4 + i;
        float rr, zz, ni, nh;
        unpack2(acc[i][0], rr, zz);
        unpack2(acc[i][1], ni, nh);
        rr += bj.x;  zz += bj.y;  ni += bj.z;  nh += bj.w;
        float r = 1.0f / (1.0f + expf(-rr));
        float z = 1.0f / (1.0f + expf(-zz));
        float n = tanhf(fmaf(r, nh, ni));
        float hp = hprev[m * ldh + j];
        out[m * ldo + j] = fmaf(z, hp - n, n);         // (1-z)*n + z*h
    }
}

// ---------------------------------------------------------------------------
// Host launch: 3 prep + 1 step0 + 510 steady steps + 1 tail copy.
// All graph-capturable; h_t lives in the xs output slices (no extra state).
// ---------------------------------------------------------------------------
extern "C" void kernel_launch(void* const* d_in, const int* in_sizes, int n_in,
                              void* d_out, int out_size)
{
    // Locate inputs by element count (robust to scalar-input placement):
    //   x0/h0: 131072, W_ih/W_hh: 3145728, b_ih/b_hh: 3072
    int ix0 = -1, ih0 = -1, iwih = -1, iwhh = -1, ibih = -1, ibhh = -1;
    for (int i = 0; i < n_in; i++) {
        int s = in_sizes[i];
        if      (s == BB * HH)      { if (ix0  < 0) ix0  = i; else if (ih0  < 0) ih0  = i; }
        else if (s == 3 * HH * HH)  { if (iwih < 0) iwih = i; else if (iwhh < 0) iwhh = i; }
        else if (s == 3 * HH)       { if (ibih < 0) ibih = i; else if (ibhh < 0) ibhh = i; }
    }
    const float* x0  = (const float*)d_in[ix0];
    const float* h0  = (const float*)d_in[ih0];
    const float* Wih = (const float*)d_in[iwih];
    const float* Whh = (const float*)d_in[iwhh];
    const float* bih = (const float*)d_in[ibih];
    const float* bhh = (const float*)d_in[ibhh];

    float* xs = (float*)d_out;                 // (B, T, H) then h_final (B, H)

    // Prep
    {
        int n = NG * HH;
        k_prep_wc <<<(n + 255) / 256, 256>>>(Wih, Whh);
        n = NG * 2 * HH;
        k_prep_wc0<<<(n + 255) / 256, 256>>>(Wih, Whh);
        n = BB * 2 * HH;
        k_prep_misc<<<(n + 255) / 256, 256>>>(bih, bhh, x0, h0, xs);
    }

    dim3 grid(NG / BN, BB / BM);   // (128, 2)
    dim3 block(128);

    // Step 1: h_1 = cell(x0, h0), written to xs slice t=1
    gru_step_kernel<2*HH, true><<<grid, block>>>(
        nullptr, 0, h0, HH, xs + 1 * HH, TT * HH);

    // Steps 2..511: x_t == h_t == xs slice (t-1)
    for (int t = 2; t < TT; t++) {
        const float* hp = xs + (t - 1) * HH;
        gru_step_kernel<HH, false><<<grid, block>>>(
            hp, TT * HH, hp, TT * HH, xs + t * HH, TT * HH);
    }

    // h_final = xs slice (T-1)
    k_final<<<(BB * HH + 255) / 256, 256>>>(xs);
}

// round 4
// speedup vs baseline: 7.4897x; 7.4897x over previous
#include <cuda_runtime.h>
#include <cuda_bf16.h>
#include <math.h>
#include <stdint.h>

// Problem constants
#define BB 128
#define HH 1024
#define TT 512
#define NG (4*HH)           // 4096 gate cols, interleaved n = j*4+g, g in {r,z,ni,nh}

// GEMM: D(128 x 4096) = A(128 x K)·W^T, bf16 3-term split (hi·hi + lo·hi + hi·lo)
// 128 CTAs, each Ntile=32 gate cols (8 j). K chunked by 128.
#define NCTA 128
#define KC 128
#define CH_A_ELEM 16384     // 128 x 128 bf16 per A half-image chunk
#define CH_W_ELEM 4096      // 32 x 128 bf16 per W half-image chunk

// smem layout (dynamic)
#define PST 2
#define SM_A_OFF 1024
#define SM_W_OFF (1024 + PST*65536)               // 132096
#define SMEM_TOTAL (SM_W_OFF + PST*16384)         // 164864

// ---------------------------------------------------------------------------
// Device scratch (static __device__ arrays only — no allocation)
// ---------------------------------------------------------------------------
__device__ __align__(128) __nv_bfloat16 g_Wimg [(size_t)NCTA *  8 * 2 * CH_W_ELEM]; // steady  16.8MB
__device__ __align__(128) __nv_bfloat16 g_Wimg0[(size_t)NCTA * 16 * 2 * CH_W_ELEM]; // step-0  33.6MB
__device__ __align__(128) __nv_bfloat16 g_Aimg [2][8 * 2 * CH_A_ELEM];               // ping-pong A images
__device__ __align__(128) __nv_bfloat16 g_A0img[16 * 2 * CH_A_ELEM];                 // step-0 A image
__device__ float g_bci[NG];

// ---------------------------------------------------------------------------
// Helpers
// ---------------------------------------------------------------------------
__device__ __forceinline__ uint32_t smem_u32(const void* p) {
    uint32_t a;
    asm("{ .reg .u64 t; cvta.to.shared.u64 t, %1; cvt.u32.u64 %0, t; }" : "=r"(a) : "l"(p));
    return a;
}

#define MBAR_INIT(a, c) asm volatile("mbarrier.init.shared.b64 [%0], %1;" :: "r"(a), "r"(c) : "memory")
#define MBAR_EXPECT_TX(a, b) asm volatile("mbarrier.arrive.expect_tx.shared.b64 _, [%0], %1;" :: "r"(a), "r"(b) : "memory")
#define MBAR_ARRIVE(a) asm volatile("mbarrier.arrive.shared.b64 _, [%0];" :: "r"(a) : "memory")
#define MBAR_WAIT(a, ph) do { \
    uint32_t _m = (a), _p = (ph), _d; \
    asm volatile("{ .reg .pred p; mbarrier.try_wait.parity.acquire.cta.shared::cta.b64 p, [%1], %2; selp.b32 %0,1,0,p; }" \
        : "=r"(_d) : "r"(_m), "r"(_p) : "memory"); \
    if (!_d) { asm volatile("{ .reg .pred P1; W%=: mbarrier.try_wait.parity.acquire.cta.shared::cta.b64 P1, [%0], %1, 0x989680; @P1 bra.uni D%=; bra.uni W%=; D%=: }" \
        :: "r"(_m), "r"(_p) : "memory"); } \
} while (0)

#define BULK_G2S(dst, src, bytes, mbar) \
    asm volatile("cp.async.bulk.shared::cluster.global.mbarrier::complete_tx::bytes [%0], [%1], %2, [%3];" \
        :: "r"(dst), "l"(src), "r"(bytes), "r"(mbar) : "memory")

__device__ __forceinline__ void ldsm4(uint32_t* r, uint32_t addr) {
    asm volatile("ldmatrix.sync.aligned.m8n8.x4.shared.b16 {%0,%1,%2,%3}, [%4];"
        : "=r"(r[0]), "=r"(r[1]), "=r"(r[2]), "=r"(r[3]) : "r"(addr));
}
__device__ __forceinline__ void mma_bf16(float* c, const uint32_t* a, const uint32_t* b) {
    asm volatile("mma.sync.aligned.m16n8k16.row.col.f32.bf16.bf16.f32 "
        "{%0,%1,%2,%3}, {%4,%5,%6,%7}, {%8,%9}, {%0,%1,%2,%3};"
        : "+f"(c[0]), "+f"(c[1]), "+f"(c[2]), "+f"(c[3])
        : "r"(a[0]), "r"(a[1]), "r"(a[2]), "r"(a[3]), "r"(b[0]), "r"(b[1]));
}

// swizzled element offset within a [rows x 128] bf16 chunk image:
// 16B unit u = c/8 stored at u ^ (r & 7)
__device__ __forceinline__ int img_elem(int r, int c) {
    return r * 128 + (((c >> 3) ^ (r & 7)) << 3) + (c & 7);
}

// ---------------------------------------------------------------------------
// Prep: weight combine
// ---------------------------------------------------------------------------
__device__ __forceinline__ float combineW(const float* Wih, const float* Whh, int g, int j, int k) {
    if (g == 0) return Wih[j*HH + k]          + Whh[j*HH + k];
    if (g == 1) return Wih[(HH + j)*HH + k]   + Whh[(HH + j)*HH + k];
    if (g == 2) return Wih[(2*HH + j)*HH + k];
    return             Whh[(2*HH + j)*HH + k];
}
__device__ __forceinline__ float combineW0(const float* Wih, const float* Whh, int g, int j, int k) {
    if (k < HH) {
        if (g == 0) return Wih[j*HH + k];
        if (g == 1) return Wih[(HH + j)*HH + k];
        if (g == 2) return Wih[(2*HH + j)*HH + k];
        return 0.0f;
    } else {
        int kk = k - HH;
        if (g == 0) return Whh[j*HH + kk];
        if (g == 1) return Whh[(HH + j)*HH + kk];
        if (g == 2) return 0.0f;
        return Whh[(2*HH + j)*HH + kk];
    }
}

// Steady W image: [cta][kc 0..7][hi|lo][32 x 128 swizzled bf16]
__global__ void k_prep_wimg(const float* __restrict__ Wih, const float* __restrict__ Whh) {
    size_t idx = (size_t)blockIdx.x * blockDim.x + threadIdx.x;
    if (idx >= (size_t)NCTA * 8 * 2 * CH_W_ELEM) return;
    int e  = idx & (CH_W_ELEM - 1);            // r*128 + c position (pre-swizzle)
    int h  = (idx >> 12) & 1;
    int kc = (idx >> 13) & 7;
    int n  = (int)(idx >> 16);
    int r = e >> 7, c = e & 127;
    int R = n*32 + r, j = R >> 2, g = R & 3;
    float w = combineW(Wih, Whh, g, j, kc*128 + c);
    __nv_bfloat16 hi = __float2bfloat16_rn(w);
    __nv_bfloat16 v = h ? __float2bfloat16_rn(w - __bfloat162float(hi)) : hi;
    g_Wimg[(((size_t)n*8 + kc)*2 + h) * CH_W_ELEM + img_elem(r, c)] = v;
}

// Step-0 W image: K=2048 -> 16 chunks
__global__ void k_prep_wimg0(const float* __restrict__ Wih, const float* __restrict__ Whh) {
    size_t idx = (size_t)blockIdx.x * blockDim.x + threadIdx.x;
    if (idx >= (size_t)NCTA * 16 * 2 * CH_W_ELEM) return;
    int e  = idx & (CH_W_ELEM - 1);
    int h  = (idx >> 12) & 1;
    int kc = (idx >> 13) & 15;
    int n  = (int)(idx >> 17);
    int r = e >> 7, c = e & 127;
    int R = n*32 + r, j = R >> 2, g = R & 3;
    float w = combineW0(Wih, Whh, g, j, kc*128 + c);
    __nv_bfloat16 hi = __float2bfloat16_rn(w);
    __nv_bfloat16 v = h ? __float2bfloat16_rn(w - __bfloat162float(hi)) : hi;
    g_Wimg0[(((size_t)n*16 + kc)*2 + h) * CH_W_ELEM + img_elem(r, c)] = v;
}

// Step-0 A image: [kc 0..15][hi|lo][128 x 128], A0 = [x0 | h0]
__global__ void k_prep_a0(const float* __restrict__ x0, const float* __restrict__ h0) {
    int idx = blockIdx.x * blockDim.x + threadIdx.x;
    if (idx >= 16 * 2 * CH_A_ELEM) return;
    int e  = idx & (CH_A_ELEM - 1);
    int h  = (idx >> 14) & 1;
    int kc = idx >> 15;
    int m = e >> 7, c = e & 127;
    int k = kc*128 + c;
    float s = (k < HH) ? x0[m*HH + k] : h0[m*HH + (k - HH)];
    __nv_bfloat16 hi = __float2bfloat16_rn(s);
    __nv_bfloat16 v = h ? __float2bfloat16_rn(s - __bfloat162float(hi)) : hi;
    g_A0img[(kc*2 + h) * CH_A_ELEM + img_elem(m, c)] = v;
}

__global__ void k_prep_misc(const float* __restrict__ bih, const float* __restrict__ bhh,
                            const float* __restrict__ x0, float* __restrict__ xs) {
    int idx = blockIdx.x * blockDim.x + threadIdx.x;
    if (idx < NG) {
        int g = idx & 3, j = idx >> 2;
        float v;
        if      (g == 0) v = bih[j]        + bhh[j];
        else if (g == 1) v = bih[HH + j]   + bhh[HH + j];
        else if (g == 2) v = bih[2*HH + j];
        else             v = bhh[2*HH + j];
        g_bci[idx] = v;
    }
    if (idx < BB * HH) {
        int b = idx >> 10, j = idx & (HH - 1);
        xs[b * (TT*HH) + j] = x0[idx];
    }
}

__global__ void k_final(float* __restrict__ outbase) {
    int idx = blockIdx.x * blockDim.x + threadIdx.x;
    if (idx >= BB * HH) return;
    int b = idx >> 10, j = idx & (HH - 1);
    outbase[(size_t)BB * TT * HH + idx] = outbase[b * (TT*HH) + (TT - 1) * HH + j];
}

// ---------------------------------------------------------------------------
// Fused GRU step: warp 8 = bulk-load producer, warps 0-7 = HMMA, fused epilogue.
// NC = K chunks (8 steady / 16 step-0).
// ---------------------------------------------------------------------------
template<int NC>
__global__ void __launch_bounds__(288, 1)
gru_step_mma(const __nv_bfloat16* __restrict__ Aimg,
             const __nv_bfloat16* __restrict__ Wimg,
             const float* __restrict__ hprev, int ldh,
             float* __restrict__ xs_out,
             __nv_bfloat16* __restrict__ Aout)
{
    extern __shared__ __align__(128) char smem[];
    const uint32_t sb = smem_u32(smem);
    const int tid = threadIdx.x, wid = tid >> 5, lane = tid & 31;
    const int n = blockIdx.x;

    const uint32_t bar_full0  = sb + 8;   // full[0], full[1]
    const uint32_t bar_empty0 = sb + 24;  // empty[0], empty[1]

    if (tid == 0) {
        MBAR_INIT(bar_full0,      1); MBAR_INIT(bar_full0 + 8,  1);
        MBAR_INIT(bar_empty0,     8); MBAR_INIT(bar_empty0 + 8, 8);
    }
    __syncthreads();

    float acc[2][2][4];
#pragma unroll
    for (int mi = 0; mi < 2; mi++)
#pragma unroll
        for (int ni = 0; ni < 2; ni++)
#pragma unroll
            for (int q = 0; q < 4; q++) acc[mi][ni][q] = 0.0f;

    if (wid == 8) {
        if (lane == 0) {
            for (int c = 0; c < NC; c++) {
                int s = c & 1, u = c >> 1;
                if (u > 0) MBAR_WAIT(bar_empty0 + s*8, (u - 1) & 1);
                MBAR_EXPECT_TX(bar_full0 + s*8, 81920u);
                BULK_G2S(sb + SM_A_OFF + s*65536,
                         Aimg + (size_t)c * (2*CH_A_ELEM), 65536u, bar_full0 + s*8);
                BULK_G2S(sb + SM_W_OFF + s*16384,
                         Wimg + ((size_t)n * NC + c) * (2*CH_W_ELEM), 16384u, bar_full0 + s*8);
            }
        }
    } else {
        // warp tile: wm = wid&3 (32 rows), wn = wid>>2 (16 gate cols)
        const int wm = wid & 3, wn = wid >> 2;
        const int ra  = wm*32 + (lane & 15);          // A row (mi*16 added in-loop)
        const int ha  = lane >> 4;                    // A k-half
        const int rw  = wn*16 + ((lane >> 4) << 3) + (lane & 7);   // W row (n)
        const int hw  = (lane >> 3) & 1;              // W k-half
        const uint32_t a_row0 = (uint32_t)(ra * 256);
        const uint32_t a_row1 = (uint32_t)((ra + 16) * 256);
        const int a_sw = ra & 7;                      // (ra+16)&7 identical
        const uint32_t w_row = (uint32_t)(rw * 256);
        const int w_sw = rw & 7;

        for (int c = 0; c < NC; c++) {
            int s = c & 1, u = c >> 1;
            MBAR_WAIT(bar_full0 + s*8, u & 1);
            const uint32_t sA = sb + SM_A_OFF + s*65536;   // hi at +0, lo at +32768
            const uint32_t sW = sb + SM_W_OFF + s*16384;   // hi at +0, lo at +8192
#pragma unroll
            for (int kk = 0; kk < 8; kk++) {
                const uint32_t ua = (uint32_t)(((kk*2 + ha) ^ a_sw) << 4);
                const uint32_t uw = (uint32_t)(((kk*2 + hw) ^ w_sw) << 4);
                uint32_t ahi[2][4], alo[2][4], wh[4], wl[4];
                ldsm4(ahi[0], sA + a_row0 + ua);
                ldsm4(ahi[1], sA + a_row1 + ua);
                ldsm4(alo[0], sA + 32768 + a_row0 + ua);
                ldsm4(alo[1], sA + 32768 + a_row1 + ua);
                ldsm4(wh, sW + w_row + uw);
                ldsm4(wl, sW + 8192 + w_row + uw);
#pragma unroll
                for (int mi = 0; mi < 2; mi++)
#pragma unroll
                    for (int ni = 0; ni < 2; ni++) {
                        mma_bf16(acc[mi][ni], ahi[mi], &wh[ni*2]);
                        mma_bf16(acc[mi][ni], alo[mi], &wh[ni*2]);
                        mma_bf16(acc[mi][ni], ahi[mi], &wl[ni*2]);
                    }
            }
            __syncwarp();
            if (lane == 0) MBAR_ARRIVE(bar_empty0 + s*8);
        }
    }

    __syncthreads();

    // D exchange through smem (reuse stage-0 A buffer), padded stride 36 floats
    float* Dsm = (float*)(smem + SM_A_OFF);
    if (wid < 8) {
        const int wm = wid & 3, wn = wid >> 2;
#pragma unroll
        for (int mi = 0; mi < 2; mi++)
#pragma unroll
            for (int ni = 0; ni < 2; ni++) {
                int row = wm*32 + mi*16 + (lane >> 2);
                int col = wn*16 + ni*8 + (lane & 3)*2;
                Dsm[row*36 + col]       = acc[mi][ni][0];
                Dsm[row*36 + col + 1]   = acc[mi][ni][1];
                Dsm[(row+8)*36 + col]   = acc[mi][ni][2];
                Dsm[(row+8)*36 + col+1] = acc[mi][ni][3];
            }
    }
    __syncthreads();

    // GRU epilogue: 1024 outputs (128 m x 8 j), 4 per thread for tid<256
    if (tid < 256) {
        const int m  = tid & 127;
        const int jg = tid >> 7;              // 0 or 1
        const int jj0 = jg * 4;
        const float4 hp4 = *(const float4*)(hprev + (size_t)m * ldh + n*8 + jj0);
        const float hps[4] = { hp4.x, hp4.y, hp4.z, hp4.w };
        float hv4[4];
#pragma unroll
        for (int q = 0; q < 4; q++) {
            const int jj = jj0 + q;
            const float4 b4 = *(const float4*)(g_bci + n*32 + jj*4);
            float rr = Dsm[m*36 + jj*4 + 0] + b4.x;
            float zz = Dsm[m*36 + jj*4 + 1] + b4.y;
            float ni_ = Dsm[m*36 + jj*4 + 2] + b4.z;
            float nh = Dsm[m*36 + jj*4 + 3] + b4.w;
            float r = 1.0f / (1.0f + expf(-rr));
            float z = 1.0f / (1.0f + expf(-zz));
            float nn = tanhf(fmaf(r, nh, ni_));
            float hv = fmaf(z, hps[q] - nn, nn);
            hv4[q] = hv;
            // next-step A image (hi/lo), swizzled
            const int j = n*8 + jj;
            const int kc = j >> 7, cc = j & 127;
            __nv_bfloat16 hi = __float2bfloat16_rn(hv);
            __nv_bfloat16 lo = __float2bfloat16_rn(hv - __bfloat162float(hi));
            const int eo = img_elem(m, cc);
            Aout[(kc*2 + 0) * CH_A_ELEM + eo] = hi;
            Aout[(kc*2 + 1) * CH_A_ELEM + eo] = lo;
        }
        *(float4*)(xs_out + (size_t)m * (TT*HH) + n*8 + jj0) =
            make_float4(hv4[0], hv4[1], hv4[2], hv4[3]);
    }
}

// ---------------------------------------------------------------------------
// Host launch
// ---------------------------------------------------------------------------
extern "C" void kernel_launch(void* const* d_in, const int* in_sizes, int n_in,
                              void* d_out, int out_size)
{
    int ix0 = -1, ih0 = -1, iwih = -1, iwhh = -1, ibih = -1, ibhh = -1;
    for (int i = 0; i < n_in; i++) {
        int s = in_sizes[i];
        if      (s == BB * HH)     { if (ix0  < 0) ix0  = i; else if (ih0  < 0) ih0  = i; }
        else if (s == 3 * HH * HH) { if (iwih < 0) iwih = i; else if (iwhh < 0) iwhh = i; }
        else if (s == 3 * HH)      { if (ibih < 0) ibih = i; else if (ibhh < 0) ibhh = i; }
    }
    const float* x0  = (const float*)d_in[ix0];
    const float* h0  = (const float*)d_in[ih0];
    const float* Wih = (const float*)d_in[iwih];
    const float* Whh = (const float*)d_in[iwhh];
    const float* bih = (const float*)d_in[ibih];
    const float* bhh = (const float*)d_in[ibhh];
    float* xs = (float*)d_out;

    cudaFuncSetAttribute(gru_step_mma<8>,  cudaFuncAttributeMaxDynamicSharedMemorySize, SMEM_TOTAL);
    cudaFuncSetAttribute(gru_step_mma<16>, cudaFuncAttributeMaxDynamicSharedMemorySize, SMEM_TOTAL);

    // Prep
    {
        size_t nw = (size_t)NCTA * 8 * 2 * CH_W_ELEM;
        k_prep_wimg <<<(unsigned)((nw + 255) / 256), 256>>>(Wih, Whh);
        size_t nw0 = (size_t)NCTA * 16 * 2 * CH_W_ELEM;
        k_prep_wimg0<<<(unsigned)((nw0 + 255) / 256), 256>>>(Wih, Whh);
        k_prep_a0   <<<(16 * 2 * CH_A_ELEM + 255) / 256, 256>>>(x0, h0);
        k_prep_misc <<<(BB * HH + 255) / 256, 256>>>(bih, bhh, x0, xs);
    }

    __nv_bfloat16 *aimg0, *a0img, *wimg, *wimg0;
    cudaGetSymbolAddress((void**)&aimg0, g_Aimg);
    cudaGetSymbolAddress((void**)&a0img, g_A0img);
    cudaGetSymbolAddress((void**)&wimg,  g_Wimg);
    cudaGetSymbolAddress((void**)&wimg0, g_Wimg0);
    __nv_bfloat16* aimg[2] = { aimg0, aimg0 + 8 * 2 * CH_A_ELEM };

    // Step t=1: A0=[x0|h0], K=2048 (16 chunks); writes xs[:,1,:] and A image[0]
    gru_step_mma<16><<<NCTA, 288, SMEM_TOTAL>>>(a0img, wimg0, h0, HH,
                                                xs + 1 * HH, aimg[0]);
    // Steps t=2..511
    for (int t = 2; t < TT; t++) {
        gru_step_mma<8><<<NCTA, 288, SMEM_TOTAL>>>(aimg[t & 1], wimg,
                                                   xs + (t - 1) * HH, TT * HH,
                                                   xs + t * HH, aimg[(t + 1) & 1]);
    }
    k_final<<<(BB * HH + 255) / 256, 256>>>(xs);
}

// round 5
// speedup vs baseline: 7.7864x; 1.0396x over previous
#include <cuda_runtime.h>
#include <cuda_bf16.h>
#include <math.h>
#include <stdint.h>

// Problem constants
#define BB 128
#define HH 1024
#define TT 512
#define NG (4*HH)           // 4096 gate cols, interleaved n = j*4+g, g in {r,z,ni,nh}

#define NCTA 128

// step-1 (old-style) kernel constants: 128-col chunks
#define CH_A_ELEM 16384     // 128 x 128 bf16
#define CH_W_ELEM 4096      // 32 x 128 bf16
#define PST 2
#define SM_A_OFF 1024
#define SM_W_OFF (1024 + PST*65536)
#define SMEM_TOTAL1 (SM_W_OFF + PST*16384)        // 164864

// persistent kernel: 64-col A chunks, W resident in smem
// smem: [0,1024) ctrl | [1024, +3*32768) A stages (stage0 reused as D-exchange) | W 131072
#define P_SA 1024
#define P_SW (1024 + 3*32768)                     // 99328
#define SMEM_TOTALP (P_SW + 131072)               // 230400

// ---------------------------------------------------------------------------
// Device scratch
// ---------------------------------------------------------------------------
__device__ __align__(128) __nv_bfloat16 g_Wimg [(size_t)NCTA * 16 * 2 * 2048];    // steady W, new layout 16.8MB
__device__ __align__(128) __nv_bfloat16 g_Wimg0[(size_t)NCTA * 16 * 2 * CH_W_ELEM]; // step-1 W (old layout) 33.6MB
__device__ __align__(128) __nv_bfloat16 g_Aimg [2][16 * 16384];                   // ping-pong A images (new layout, 512KB each)
__device__ __align__(128) __nv_bfloat16 g_A0img[16 * 2 * CH_A_ELEM];              // step-1 A image (old layout)
__device__ float g_bci[NG];
__device__ unsigned g_bar_count = 0;
__device__ unsigned g_bar_gen   = 0;

// ---------------------------------------------------------------------------
// Helpers
// ---------------------------------------------------------------------------
__device__ __forceinline__ uint32_t smem_u32(const void* p) {
    uint32_t a;
    asm("{ .reg .u64 t; cvta.to.shared.u64 t, %1; cvt.u32.u64 %0, t; }" : "=r"(a) : "l"(p));
    return a;
}

#define MBAR_INIT(a, c) asm volatile("mbarrier.init.shared.b64 [%0], %1;" :: "r"(a), "r"(c) : "memory")
#define MBAR_EXPECT_TX(a, b) asm volatile("mbarrier.arrive.expect_tx.shared.b64 _, [%0], %1;" :: "r"(a), "r"(b) : "memory")
#define MBAR_ARRIVE(a) asm volatile("mbarrier.arrive.shared.b64 _, [%0];" :: "r"(a) : "memory")
#define MBAR_WAIT(a, ph) do { \
    uint32_t _m = (a), _p = (ph), _d; \
    asm volatile("{ .reg .pred p; mbarrier.try_wait.parity.acquire.cta.shared::cta.b64 p, [%1], %2; selp.b32 %0,1,0,p; }" \
        : "=r"(_d) : "r"(_m), "r"(_p) : "memory"); \
    if (!_d) { asm volatile("{ .reg .pred P1; W%=: mbarrier.try_wait.parity.acquire.cta.shared::cta.b64 P1, [%0], %1, 0x989680; @P1 bra.uni D%=; bra.uni W%=; D%=: }" \
        :: "r"(_m), "r"(_p) : "memory"); } \
} while (0)

#define BULK_G2S(dst, src, bytes, mbar) \
    asm volatile("cp.async.bulk.shared::cluster.global.mbarrier::complete_tx::bytes [%0], [%1], %2, [%3];" \
        :: "r"(dst), "l"(src), "r"(bytes), "r"(mbar) : "memory")

__device__ __forceinline__ void ldsm4(uint32_t* r, uint32_t addr) {
    asm volatile("ldmatrix.sync.aligned.m8n8.x4.shared.b16 {%0,%1,%2,%3}, [%4];"
        : "=r"(r[0]), "=r"(r[1]), "=r"(r[2]), "=r"(r[3]) : "r"(addr));
}
__device__ __forceinline__ void mma_bf16(float* c, const uint32_t* a, const uint32_t* b) {
    asm volatile("mma.sync.aligned.m16n8k16.row.col.f32.bf16.bf16.f32 "
        "{%0,%1,%2,%3}, {%4,%5,%6,%7}, {%8,%9}, {%0,%1,%2,%3};"
        : "+f"(c[0]), "+f"(c[1]), "+f"(c[2]), "+f"(c[3])
        : "r"(a[0]), "r"(a[1]), "r"(a[2]), "r"(a[3]), "r"(b[0]), "r"(b[1]));
}

// 128-byte-row swizzles (8 16B units per row): unit u at u ^ (row & 7)
__device__ __forceinline__ int img_elem(int r, int c) {    // 128-col bf16 rows (old layout)
    return r * 128 + (((c >> 3) ^ (r & 7)) << 3) + (c & 7);
}
__device__ __forceinline__ int img64(int r, int c) {       // 64-col bf16 rows (new layout)
    return r * 64 + (((c >> 3) ^ (r & 7)) << 3) + (c & 7);
}
__device__ __forceinline__ uint32_t pack_bf2(float a, float b) {
    __nv_bfloat162 t = __floats2bfloat162_rn(a, b);
    return *(uint32_t*)&t;
}

// Grid-wide barrier (all NCTA CTAs co-resident; generation counter in gmem)
__device__ __forceinline__ void grid_barrier(int tid) {
    __threadfence();
    asm volatile("fence.proxy.async;" ::: "memory");
    __syncthreads();
    if (tid == 0) {
        unsigned gen0;
        asm volatile("ld.acquire.gpu.u32 %0, [%1];" : "=r"(gen0) : "l"(&g_bar_gen));
        if (atomicAdd(&g_bar_count, 1u) == NCTA - 1) {
            g_bar_count = 0;
            asm volatile("st.release.gpu.u32 [%0], %1;" :: "l"(&g_bar_gen), "r"(gen0 + 1) : "memory");
        } else {
            unsigned g;
            do {
                __nanosleep(32);
                asm volatile("ld.acquire.gpu.u32 %0, [%1];" : "=r"(g) : "l"(&g_bar_gen));
            } while (g == gen0);
        }
    }
    __syncthreads();
}

// ---------------------------------------------------------------------------
// Weight combine
// ---------------------------------------------------------------------------
__device__ __forceinline__ float combineW(const float* Wih, const float* Whh, int g, int j, int k) {
    if (g == 0) return Wih[j*HH + k]          + Whh[j*HH + k];
    if (g == 1) return Wih[(HH + j)*HH + k]   + Whh[(HH + j)*HH + k];
    if (g == 2) return Wih[(2*HH + j)*HH + k];
    return             Whh[(2*HH + j)*HH + k];
}
__device__ __forceinline__ float combineW0(const float* Wih, const float* Whh, int g, int j, int k) {
    if (k < HH) {
        if (g == 0) return Wih[j*HH + k];
        if (g == 1) return Wih[(HH + j)*HH + k];
        if (g == 2) return Wih[(2*HH + j)*HH + k];
        return 0.0f;
    } else {
        int kk = k - HH;
        if (g == 0) return Whh[j*HH + kk];
        if (g == 1) return Whh[(HH + j)*HH + kk];
        if (g == 2) return 0.0f;
        return Whh[(2*HH + j)*HH + kk];
    }
}

// Steady W (new layout): [cta][kc 0..15][hi|lo][32 x 64 bf16 swizzled]
__global__ void k_prep_wimg(const float* __restrict__ Wih, const float* __restrict__ Whh) {
    int idx = blockIdx.x * blockDim.x + threadIdx.x;
    if (idx >= NCTA * 16 * 2 * 2048) return;
    int e  = idx & 2047;
    int h  = (idx >> 11) & 1;
    int kc = (idx >> 12) & 15;
    int n  = idx >> 16;
    int r = e >> 6, c = e & 63;
    int R = n*32 + r, j = R >> 2, g = R & 3;
    float w = combineW(Wih, Whh, g, j, kc*64 + c);
    __nv_bfloat16 hi = __float2bfloat16_rn(w);
    __nv_bfloat16 v = h ? __float2bfloat16_rn(w - __bfloat162float(hi)) : hi;
    g_Wimg[((size_t)((n*16 + kc)*2 + h)) * 2048 + img64(r, c)] = v;
}

// Step-1 W (old layout): [cta][kc 0..15][hi|lo][32 x 128 bf16 swizzled], K=2048
__global__ void k_prep_wimg0(const float* __restrict__ Wih, const float* __restrict__ Whh) {
    size_t idx = (size_t)blockIdx.x * blockDim.x + threadIdx.x;
    if (idx >= (size_t)NCTA * 16 * 2 * CH_W_ELEM) return;
    int e  = idx & (CH_W_ELEM - 1);
    int h  = (idx >> 12) & 1;
    int kc = (idx >> 13) & 15;
    int n  = (int)(idx >> 17);
    int r = e >> 7, c = e & 127;
    int R = n*32 + r, j = R >> 2, g = R & 3;
    float w = combineW0(Wih, Whh, g, j, kc*128 + c);
    __nv_bfloat16 hi = __float2bfloat16_rn(w);
    __nv_bfloat16 v = h ? __float2bfloat16_rn(w - __bfloat162float(hi)) : hi;
    g_Wimg0[(((size_t)n*16 + kc)*2 + h) * CH_W_ELEM + img_elem(r, c)] = v;
}

// Step-1 A image (old layout): [kc 0..15][hi|lo][128 x 128], A0 = [x0 | h0]
__global__ void k_prep_a0(const float* __restrict__ x0, const float* __restrict__ h0) {
    int idx = blockIdx.x * blockDim.x + threadIdx.x;
    if (idx >= 16 * 2 * CH_A_ELEM) return;
    int e  = idx & (CH_A_ELEM - 1);
    int h  = (idx >> 14) & 1;
    int kc = idx >> 15;
    int m = e >> 7, c = e & 127;
    int k = kc*128 + c;
    float s = (k < HH) ? x0[m*HH + k] : h0[m*HH + (k - HH)];
    __nv_bfloat16 hi = __float2bfloat16_rn(s);
    __nv_bfloat16 v = h ? __float2bfloat16_rn(s - __bfloat162float(hi)) : hi;
    g_A0img[(kc*2 + h) * CH_A_ELEM + img_elem(m, c)] = v;
}

__global__ void k_prep_misc(const float* __restrict__ bih, const float* __restrict__ bhh,
                            const float* __restrict__ x0, float* __restrict__ xs) {
    int idx = blockIdx.x * blockDim.x + threadIdx.x;
    if (idx == 0) { g_bar_count = 0; g_bar_gen = 0; }
    if (idx < NG) {
        int g = idx & 3, j = idx >> 2;
        float v;
        if      (g == 0) v = bih[j]        + bhh[j];
        else if (g == 1) v = bih[HH + j]   + bhh[HH + j];
        else if (g == 2) v = bih[2*HH + j];
        else             v = bhh[2*HH + j];
        g_bci[idx] = v;
    }
    if (idx < BB * HH) {
        int b = idx >> 10, j = idx & (HH - 1);
        xs[b * (TT*HH) + j] = x0[idx];
    }
}

__global__ void k_final(float* __restrict__ outbase) {
    int idx = blockIdx.x * blockDim.x + threadIdx.x;
    if (idx >= BB * HH) return;
    int b = idx >> 10, j = idx & (HH - 1);
    outbase[(size_t)BB * TT * HH + idx] = outbase[b * (TT*HH) + (TT - 1) * HH + j];
}

// ---------------------------------------------------------------------------
// Step-1 kernel (K=2048, old streamed layout). Writes xs[:,1,:] + new-layout A image.
// ---------------------------------------------------------------------------
__global__ void __launch_bounds__(288, 1)
gru_step1(const __nv_bfloat16* __restrict__ Aimg,
          const __nv_bfloat16* __restrict__ Wimg,
          float* __restrict__ xs_out,
          __nv_bfloat16* __restrict__ Aout)
{
    constexpr int NC = 16;
    extern __shared__ __align__(128) char smem[];
    const uint32_t sb = smem_u32(smem);
    const int tid = threadIdx.x, wid = tid >> 5, lane = tid & 31;
    const int n = blockIdx.x;

    const uint32_t bar_full0  = sb + 8;
    const uint32_t bar_empty0 = sb + 24;

    if (tid == 0) {
        MBAR_INIT(bar_full0,      1); MBAR_INIT(bar_full0 + 8,  1);
        MBAR_INIT(bar_empty0,     8); MBAR_INIT(bar_empty0 + 8, 8);
    }
    __syncthreads();

    float acc[2][2][4];
#pragma unroll
    for (int mi = 0; mi < 2; mi++)
#pragma unroll
        for (int ni = 0; ni < 2; ni++)
#pragma unroll
            for (int q = 0; q < 4; q++) acc[mi][ni][q] = 0.0f;

    if (wid == 8) {
        if (lane == 0) {
            for (int c = 0; c < NC; c++) {
                int s = c & 1, u = c >> 1;
                if (u > 0) MBAR_WAIT(bar_empty0 + s*8, (u - 1) & 1);
                MBAR_EXPECT_TX(bar_full0 + s*8, 81920u);
                BULK_G2S(sb + SM_A_OFF + s*65536,
                         Aimg + (size_t)c * (2*CH_A_ELEM), 65536u, bar_full0 + s*8);
                BULK_G2S(sb + SM_W_OFF + s*16384,
                         Wimg + ((size_t)n * NC + c) * (2*CH_W_ELEM), 16384u, bar_full0 + s*8);
            }
        }
    } else {
        const int wm = wid & 3, wn = wid >> 2;
        const int ra  = wm*32 + (lane & 15);
        const int ha  = lane >> 4;
        const int rw  = wn*16 + ((lane >> 4) << 3) + (lane & 7);
        const int hw  = (lane >> 3) & 1;
        const uint32_t a_row0 = (uint32_t)(ra * 256);
        const uint32_t a_row1 = (uint32_t)((ra + 16) * 256);
        const int a_sw = ra & 7;
        const uint32_t w_row = (uint32_t)(rw * 256);
        const int w_sw = rw & 7;

        for (int c = 0; c < NC; c++) {
            int s = c & 1, u = c >> 1;
            MBAR_WAIT(bar_full0 + s*8, u & 1);
            const uint32_t sA = sb + SM_A_OFF + s*65536;
            const uint32_t sW = sb + SM_W_OFF + s*16384;
#pragma unroll
            for (int kk = 0; kk < 8; kk++) {
                const uint32_t ua = (uint32_t)(((kk*2 + ha) ^ a_sw) << 4);
                const uint32_t uw = (uint32_t)(((kk*2 + hw) ^ w_sw) << 4);
                uint32_t ahi[2][4], alo[2][4], wh[4], wl[4];
                ldsm4(ahi[0], sA + a_row0 + ua);
                ldsm4(ahi[1], sA + a_row1 + ua);
                ldsm4(alo[0], sA + 32768 + a_row0 + ua);
                ldsm4(alo[1], sA + 32768 + a_row1 + ua);
                ldsm4(wh, sW + w_row + uw);
                ldsm4(wl, sW + 8192 + w_row + uw);
#pragma unroll
                for (int mi = 0; mi < 2; mi++)
#pragma unroll
                    for (int ni = 0; ni < 2; ni++) {
                        mma_bf16(acc[mi][ni], ahi[mi], &wh[ni*2]);
                        mma_bf16(acc[mi][ni], alo[mi], &wh[ni*2]);
                        mma_bf16(acc[mi][ni], ahi[mi], &wl[ni*2]);
                    }
            }
            __syncwarp();
            if (lane == 0) MBAR_ARRIVE(bar_empty0 + s*8);
        }
    }

    __syncthreads();
    float* Dsm = (float*)(smem + SM_A_OFF);
    if (wid < 8) {
        const int wm = wid & 3, wn = wid >> 2;
#pragma unroll
        for (int mi = 0; mi < 2; mi++)
#pragma unroll
            for (int ni = 0; ni < 2; ni++) {
                int row = wm*32 + mi*16 + (lane >> 2);
                int col = wn*16 + ni*8 + (lane & 3)*2;
                Dsm[row*36 + col]       = acc[mi][ni][0];
                Dsm[row*36 + col + 1]   = acc[mi][ni][1];
                Dsm[(row+8)*36 + col]   = acc[mi][ni][2];
                Dsm[(row+8)*36 + col+1] = acc[mi][ni][3];
            }
    }
    __syncthreads();

    if (tid < 256) {
        const int m  = tid & 127;
        const int jj0 = (tid >> 7) * 4;
        float hv[4], lo[4];
#pragma unroll
        for (int q = 0; q < 4; q++) {
            const int jj = jj0 + q;
            const float4 b4 = *(const float4*)(g_bci + n*32 + jj*4);
            float rr = Dsm[m*36 + jj*4 + 0] + b4.x;
            float zz = Dsm[m*36 + jj*4 + 1] + b4.y;
            float ni_ = Dsm[m*36 + jj*4 + 2] + b4.z;
            float nh = Dsm[m*36 + jj*4 + 3] + b4.w;
            float r = 1.0f / (1.0f + expf(-rr));
            float z = 1.0f / (1.0f + expf(-zz));
            float nn = tanhf(fmaf(r, nh, ni_));
            // hprev comes from the bias trick? No: step-1 hprev = h0, read via xs? Passed via Aimg?
            hv[q] = nn;  // placeholder, overwritten below
        }
        // hprev for step 1 is h0; read from the A0 image is awkward — use global xs? We pass hprev via Aout? 
        // Simplest: re-derive from gmem h0 pointer passed through xs_out? We instead pass h0 separately.
        (void)lo;
        // (real epilogue in gru_step1_epi below — see note)
    }
    // NOTE: epilogue moved into the version with hprev below.
}

// The real step-1 kernel (with hprev argument). The one above is unused.
__global__ void __launch_bounds__(288, 1)
gru_step1_full(const __nv_bfloat16* __restrict__ Aimg,
               const __nv_bfloat16* __restrict__ Wimg,
               const float* __restrict__ h0,
               float* __restrict__ xs_out,
               __nv_bfloat16* __restrict__ Aout)
{
    constexpr int NC = 16;
    extern __shared__ __align__(128) char smem[];
    const uint32_t sb = smem_u32(smem);
    const int tid = threadIdx.x, wid = tid >> 5, lane = tid & 31;
    const int n = blockIdx.x;

    const uint32_t bar_full0  = sb + 8;
    const uint32_t bar_empty0 = sb + 24;

    if (tid == 0) {
        MBAR_INIT(bar_full0,      1); MBAR_INIT(bar_full0 + 8,  1);
        MBAR_INIT(bar_empty0,     8); MBAR_INIT(bar_empty0 + 8, 8);
    }
    __syncthreads();

    float acc[2][2][4];
#pragma unroll
    for (int mi = 0; mi < 2; mi++)
#pragma unroll
        for (int ni = 0; ni < 2; ni++)
#pragma unroll
            for (int q = 0; q < 4; q++) acc[mi][ni][q] = 0.0f;

    if (wid == 8) {
        if (lane == 0) {
            for (int c = 0; c < NC; c++) {
                int s = c & 1, u = c >> 1;
                if (u > 0) MBAR_WAIT(bar_empty0 + s*8, (u - 1) & 1);
                MBAR_EXPECT_TX(bar_full0 + s*8, 81920u);
                BULK_G2S(sb + SM_A_OFF + s*65536,
                         Aimg + (size_t)c * (2*CH_A_ELEM), 65536u, bar_full0 + s*8);
                BULK_G2S(sb + SM_W_OFF + s*16384,
                         Wimg + ((size_t)n * NC + c) * (2*CH_W_ELEM), 16384u, bar_full0 + s*8);
            }
        }
    } else {
        const int wm = wid & 3, wn = wid >> 2;
        const int ra  = wm*32 + (lane & 15);
        const int ha  = lane >> 4;
        const int rw  = wn*16 + ((lane >> 4) << 3) + (lane & 7);
        const int hw  = (lane >> 3) & 1;
        const uint32_t a_row0 = (uint32_t)(ra * 256);
        const uint32_t a_row1 = (uint32_t)((ra + 16) * 256);
        const int a_sw = ra & 7;
        const uint32_t w_row = (uint32_t)(rw * 256);
        const int w_sw = rw & 7;

        for (int c = 0; c < NC; c++) {
            int s = c & 1, u = c >> 1;
            MBAR_WAIT(bar_full0 + s*8, u & 1);
            const uint32_t sA = sb + SM_A_OFF + s*65536;
            const uint32_t sW = sb + SM_W_OFF + s*16384;
#pragma unroll
            for (int kk = 0; kk < 8; kk++) {
                const uint32_t ua = (uint32_t)(((kk*2 + ha) ^ a_sw) << 4);
                const uint32_t uw = (uint32_t)(((kk*2 + hw) ^ w_sw) << 4);
                uint32_t ahi[2][4], alo[2][4], wh[4], wl[4];
                ldsm4(ahi[0], sA + a_row0 + ua);
                ldsm4(ahi[1], sA + a_row1 + ua);
                ldsm4(alo[0], sA + 32768 + a_row0 + ua);
                ldsm4(alo[1], sA + 32768 + a_row1 + ua);
                ldsm4(wh, sW + w_row + uw);
                ldsm4(wl, sW + 8192 + w_row + uw);
#pragma unroll
                for (int mi = 0; mi < 2; mi++)
#pragma unroll
                    for (int ni = 0; ni < 2; ni++) {
                        mma_bf16(acc[mi][ni], ahi[mi], &wh[ni*2]);
                        mma_bf16(acc[mi][ni], alo[mi], &wh[ni*2]);
                        mma_bf16(acc[mi][ni], ahi[mi], &wl[ni*2]);
                    }
            }
            __syncwarp();
            if (lane == 0) MBAR_ARRIVE(bar_empty0 + s*8);
        }
    }

    __syncthreads();
    float* Dsm = (float*)(smem + SM_A_OFF);
    if (wid < 8) {
        const int wm = wid & 3, wn = wid >> 2;
#pragma unroll
        for (int mi = 0; mi < 2; mi++)
#pragma unroll
            for (int ni = 0; ni < 2; ni++) {
                int row = wm*32 + mi*16 + (lane >> 2);
                int col = wn*16 + ni*8 + (lane & 3)*2;
                Dsm[row*36 + col]       = acc[mi][ni][0];
                Dsm[row*36 + col + 1]   = acc[mi][ni][1];
                Dsm[(row+8)*36 + col]   = acc[mi][ni][2];
                Dsm[(row+8)*36 + col+1] = acc[mi][ni][3];
            }
    }
    __syncthreads();

    if (tid < 256) {
        const int m  = tid & 127;
        const int jj0 = (tid >> 7) * 4;
        const float4 hp4 = *(const float4*)(h0 + (size_t)m * HH + n*8 + jj0);
        const float hps[4] = { hp4.x, hp4.y, hp4.z, hp4.w };
        float hv[4], lov[4];
#pragma unroll
        for (int q = 0; q < 4; q++) {
            const int jj = jj0 + q;
            const float4 b4 = *(const float4*)(g_bci + n*32 + jj*4);
            float rr = Dsm[m*36 + jj*4 + 0] + b4.x;
            float zz = Dsm[m*36 + jj*4 + 1] + b4.y;
            float ni_ = Dsm[m*36 + jj*4 + 2] + b4.z;
            float nh = Dsm[m*36 + jj*4 + 3] + b4.w;
            float r = 1.0f / (1.0f + expf(-rr));
            float z = 1.0f / (1.0f + expf(-zz));
            float nn = tanhf(fmaf(r, nh, ni_));
            float h = fmaf(z, hps[q] - nn, nn);
            hv[q] = h;
            lov[q] = h - __bfloat162float(__float2bfloat16_rn(h));
        }
        *(float4*)(xs_out + (size_t)m * (TT*HH) + n*8 + jj0) =
            make_float4(hv[0], hv[1], hv[2], hv[3]);
        // new-layout A image write (64-col chunks)
        uint32_t base = (uint32_t)((n >> 3) * 16384 + m*64 + (((n & 7) ^ (m & 7)) << 3) + jj0);
        *(uint2*)(Aout + base)        = make_uint2(pack_bf2(hv[0], hv[1]), pack_bf2(hv[2], hv[3]));
        *(uint2*)(Aout + base + 8192) = make_uint2(pack_bf2(lov[0], lov[1]), pack_bf2(lov[2], lov[3]));
    }
}

// ---------------------------------------------------------------------------
// Persistent kernel: steps 2..511. W resident in smem, h resident in regs,
// A images streamed + ping-ponged in gmem, grid barrier between steps.
// ---------------------------------------------------------------------------
__global__ void __launch_bounds__(288, 1)
gru_persist(const __nv_bfloat16* __restrict__ Wimg,
            float* __restrict__ xs,
            __nv_bfloat16* __restrict__ aimgA,
            __nv_bfloat16* __restrict__ aimgB)
{
    extern __shared__ __align__(128) char smem[];
    const uint32_t sb = smem_u32(smem);
    const int tid = threadIdx.x, wid = tid >> 5, lane = tid & 31;
    const int n = blockIdx.x;

    const uint32_t wbar   = sb + 8;
    const uint32_t fullb  = sb + 16;   // 3 x 8B
    const uint32_t emptyb = sb + 40;   // 3 x 8B
    const uint32_t sA = sb + P_SA;
    const uint32_t sW = sb + P_SW;

    if (tid == 0) {
        MBAR_INIT(wbar, 1);
        for (int s = 0; s < 3; s++) {
            MBAR_INIT(fullb  + s*8, 1);
            MBAR_INIT(emptyb + s*8, 8);
        }
        // pre-complete empty phase 0 for all 3 stages
        for (int s = 0; s < 3; s++)
            for (int k = 0; k < 8; k++) MBAR_ARRIVE(emptyb + s*8);
    }
    __syncthreads();

    // Load resident W tile (128KB) once
    if (tid == 0) {
        MBAR_EXPECT_TX(wbar, 131072u);
        BULK_G2S(sW, Wimg + (size_t)n * 65536, 131072u, wbar);
    }
    MBAR_WAIT(wbar, 0);
    __syncthreads();

    // MMA fragment addressing constants
    const int wm = wid & 3, wn = wid >> 2;
    const int ra = wm*32 + (lane & 15);
    const int ha = lane >> 4;
    const int rw = wn*16 + ((lane >> 4) << 3) + (lane & 7);
    const int hw = (lane >> 3) & 1;
    const uint32_t aoff0 = (uint32_t)(ra * 128);
    const uint32_t aoff1 = (uint32_t)((ra + 16) * 128);
    const int a_sw = ra & 7;
    const uint32_t woff = (uint32_t)(rw * 128);
    const int w_sw = rw & 7;

    // Epilogue identity + register-resident h
    const int m = tid & 127, jj0 = ((tid >> 7) & 1) * 4;
    float hreg[4];
    float4 bj[4];
    if (tid < 256) {
        float4 h4 = *(const float4*)(xs + (size_t)m * (TT*HH) + HH + n*8 + jj0);
        hreg[0] = h4.x; hreg[1] = h4.y; hreg[2] = h4.z; hreg[3] = h4.w;
#pragma unroll
        for (int q = 0; q < 4; q++) bj[q] = *(const float4*)(g_bci + n*32 + (jj0 + q)*4);
    }

    float* Dsm = (float*)(smem + P_SA);   // reuses A stage 0 (safe: used only after all chunks consumed)

    int p_stage = 0, p_phase = 0;   // producer cursor (empty-wait parity; phase0 pre-completed)
    int c_stage = 0, c_phase = 0;   // consumer cursor (full-wait parity)

    for (int t = 2; t < TT; t++) {
        const __nv_bfloat16* Ain  = (t & 1) ? aimgB : aimgA;
        __nv_bfloat16*       Aout = (t & 1) ? aimgA : aimgB;

        float acc[2][2][4];
#pragma unroll
        for (int mi = 0; mi < 2; mi++)
#pragma unroll
            for (int ni = 0; ni < 2; ni++)
#pragma unroll
                for (int q = 0; q < 4; q++) acc[mi][ni][q] = 0.0f;

        if (wid == 8) {
            if (lane == 0) {
                for (int c = 0; c < 16; c++) {
                    int cr = (c + n) & 15;                 // rotate chunk order per CTA
                    MBAR_WAIT(emptyb + p_stage*8, p_phase);
                    MBAR_EXPECT_TX(fullb + p_stage*8, 32768u);
                    BULK_G2S(sA + p_stage*32768, Ain + (size_t)cr * 16384, 32768u, fullb + p_stage*8);
                    if (++p_stage == 3) { p_stage = 0; p_phase ^= 1; }
                }
            }
        } else {
            for (int c = 0; c < 16; c++) {
                int cr = (c + n) & 15;
                MBAR_WAIT(fullb + c_stage*8, c_phase);
                const uint32_t sAc = sA + c_stage*32768;
                const uint32_t sWc = sW + cr*8192;
#pragma unroll
                for (int kk = 0; kk < 4; kk++) {
                    const uint32_t ua = (uint32_t)(((kk*2 + ha) ^ a_sw) << 4);
                    const uint32_t uw = (uint32_t)(((kk*2 + hw) ^ w_sw) << 4);
                    uint32_t ahi0[4], ahi1[4], alo0[4], alo1[4], wh[4], wl[4];
                    ldsm4(ahi0, sAc + aoff0 + ua);
                    ldsm4(ahi1, sAc + aoff1 + ua);
                    ldsm4(alo0, sAc + 16384 + aoff0 + ua);
                    ldsm4(alo1, sAc + 16384 + aoff1 + ua);
                    ldsm4(wh, sWc + woff + uw);
                    ldsm4(wl, sWc + 4096 + woff + uw);
#pragma unroll
                    for (int ni = 0; ni < 2; ni++) {
                        mma_bf16(acc[0][ni], ahi0, &wh[ni*2]);
                        mma_bf16(acc[0][ni], alo0, &wh[ni*2]);
                        mma_bf16(acc[0][ni], ahi0, &wl[ni*2]);
                        mma_bf16(acc[1][ni], ahi1, &wh[ni*2]);
                        mma_bf16(acc[1][ni], alo1, &wh[ni*2]);
                        mma_bf16(acc[1][ni], ahi1, &wl[ni*2]);
                    }
                }
                __syncwarp();
                if (lane == 0) MBAR_ARRIVE(emptyb + c_stage*8);
                if (++c_stage == 3) { c_stage = 0; c_phase ^= 1; }
            }
        }

        __syncthreads();   // all chunks consumed; stage memory idle -> D exchange

        if (wid < 8) {
#pragma unroll
            for (int mi = 0; mi < 2; mi++)
#pragma unroll
                for (int ni = 0; ni < 2; ni++) {
                    int row = wm*32 + mi*16 + (lane >> 2);
                    int col = wn*16 + ni*8 + (lane & 3)*2;
                    Dsm[row*36 + col]       = acc[mi][ni][0];
                    Dsm[row*36 + col + 1]   = acc[mi][ni][1];
                    Dsm[(row+8)*36 + col]   = acc[mi][ni][2];
                    Dsm[(row+8)*36 + col+1] = acc[mi][ni][3];
                }
        }
        __syncthreads();

        if (tid < 256) {
            float hv[4], lov[4];
#pragma unroll
            for (int q = 0; q < 4; q++) {
                const int jj = jj0 + q;
                float rr = Dsm[m*36 + jj*4 + 0] + bj[q].x;
                float zz = Dsm[m*36 + jj*4 + 1] + bj[q].y;
                float ni_ = Dsm[m*36 + jj*4 + 2] + bj[q].z;
                float nh = Dsm[m*36 + jj*4 + 3] + bj[q].w;
                float r = 1.0f / (1.0f + expf(-rr));
                float z = 1.0f / (1.0f + expf(-zz));
                float nn = tanhf(fmaf(r, nh, ni_));
                float h = fmaf(z, hreg[q] - nn, nn);
                hv[q] = h; hreg[q] = h;
                lov[q] = h - __bfloat162float(__float2bfloat16_rn(h));
            }
            *(float4*)(xs + (size_t)m * (TT*HH) + (size_t)t * HH + n*8 + jj0) =
                make_float4(hv[0], hv[1], hv[2], hv[3]);
            uint32_t base = (uint32_t)((n >> 3) * 16384 + m*64 + (((n & 7) ^ (m & 7)) << 3) + jj0);
            *(uint2*)(Aout + base)        = make_uint2(pack_bf2(hv[0], hv[1]), pack_bf2(hv[2], hv[3]));
            *(uint2*)(Aout + base + 8192) = make_uint2(pack_bf2(lov[0], lov[1]), pack_bf2(lov[2], lov[3]));
        }

        grid_barrier(tid);
    }
}

// ---------------------------------------------------------------------------
// Host launch: 4 prep + step1 + persistent + final = 7 graph nodes.
// ---------------------------------------------------------------------------
extern "C" void kernel_launch(void* const* d_in, const int* in_sizes, int n_in,
                              void* d_out, int out_size)
{
    int ix0 = -1, ih0 = -1, iwih = -1, iwhh = -1, ibih = -1, ibhh = -1;
    for (int i = 0; i < n_in; i++) {
        int s = in_sizes[i];
        if      (s == BB * HH)     { if (ix0  < 0) ix0  = i; else if (ih0  < 0) ih0  = i; }
        else if (s == 3 * HH * HH) { if (iwih < 0) iwih = i; else if (iwhh < 0) iwhh = i; }
        else if (s == 3 * HH)      { if (ibih < 0) ibih = i; else if (ibhh < 0) ibhh = i; }
    }
    const float* x0  = (const float*)d_in[ix0];
    const float* h0  = (const float*)d_in[ih0];
    const float* Wih = (const float*)d_in[iwih];
    const float* Whh = (const float*)d_in[iwhh];
    const float* bih = (const float*)d_in[ibih];
    const float* bhh = (const float*)d_in[ibhh];
    float* xs = (float*)d_out;

    cudaFuncSetAttribute(gru_step1_full, cudaFuncAttributeMaxDynamicSharedMemorySize, SMEM_TOTAL1);
    cudaFuncSetAttribute(gru_persist,    cudaFuncAttributeMaxDynamicSharedMemorySize, SMEM_TOTALP);

    // Prep
    {
        int nw = NCTA * 16 * 2 * 2048;
        k_prep_wimg <<<(nw + 255) / 256, 256>>>(Wih, Whh);
        size_t nw0 = (size_t)NCTA * 16 * 2 * CH_W_ELEM;
        k_prep_wimg0<<<(unsigned)((nw0 + 255) / 256), 256>>>(Wih, Whh);
        k_prep_a0   <<<(16 * 2 * CH_A_ELEM + 255) / 256, 256>>>(x0, h0);
        k_prep_misc <<<(BB * HH + 255) / 256, 256>>>(bih, bhh, x0, xs);
    }

    __nv_bfloat16 *aimg0, *a0img, *wimg, *wimg0;
    cudaGetSymbolAddress((void**)&aimg0, g_Aimg);
    cudaGetSymbolAddress((void**)&a0img, g_A0img);
    cudaGetSymbolAddress((void**)&wimg,  g_Wimg);
    cudaGetSymbolAddress((void**)&wimg0, g_Wimg0);
    __nv_bfloat16* aimgA = aimg0;
    __nv_bfloat16* aimgB = aimg0 + 16 * 16384;

    // Step t=1 (K=2048): writes xs[:,1,:] + A image A (new layout)
    gru_step1_full<<<NCTA, 288, SMEM_TOTAL1>>>(a0img, wimg0, h0, xs + 1 * HH, aimgA);

    // Steps t=2..511 in one persistent kernel
    gru_persist<<<NCTA, 288, SMEM_TOTALP>>>(wimg, xs, aimgA, aimgB);

    k_final<<<(BB * HH + 255) / 256, 256>>>(xs);
}

// round 6
// speedup vs baseline: 7.8365x; 1.0064x over previous
#include <cuda_runtime.h>
#include <cuda_bf16.h>
#include <math.h>
#include <stdint.h>

// Problem constants
#define BB 128
#define HH 1024
#define TT 512
#define NG (4*HH)           // 4096 gate cols, interleaved n = j*4+g, g in {r,z,ni,nh}

#define NCTA 128

// step-1 kernel constants: 128-col chunks
#define CH_A_ELEM 16384     // 128 x 128 bf16
#define CH_W_ELEM 4096      // 32 x 128 bf16
#define SM_A_OFF 1024
#define SM_W_OFF (1024 + 2*65536)
#define SMEM_TOTAL1 (SM_W_OFF + 2*16384)          // 164864

// persistent kernel: 64-col A chunks, W resident in smem
#define P_SA 1024
#define P_SW (1024 + 3*32768)                     // 99328
#define SMEM_TOTALP (P_SW + 131072)               // 230400
#define THREADS_P 544                             // 16 MMA warps + 1 producer

// ---------------------------------------------------------------------------
// Device scratch
// ---------------------------------------------------------------------------
__device__ __align__(128) __nv_bfloat16 g_Wimg [(size_t)NCTA * 16 * 2 * 2048];      // steady W 16.8MB
__device__ __align__(128) __nv_bfloat16 g_Wimg0[(size_t)NCTA * 16 * 2 * CH_W_ELEM]; // step-1 W 33.6MB
__device__ __align__(128) __nv_bfloat16 g_Aimg [2][16 * 16384];                     // ping-pong A images
__device__ __align__(128) __nv_bfloat16 g_A0img[16 * 2 * CH_A_ELEM];                // step-1 A image
__device__ float g_bci[NG];
__device__ unsigned g_bar_count = 0;
__device__ unsigned g_bar_gen   = 0;

// ---------------------------------------------------------------------------
// Helpers
// ---------------------------------------------------------------------------
__device__ __forceinline__ uint32_t smem_u32(const void* p) {
    uint32_t a;
    asm("{ .reg .u64 t; cvta.to.shared.u64 t, %1; cvt.u32.u64 %0, t; }" : "=r"(a) : "l"(p));
    return a;
}

#define MBAR_INIT(a, c) asm volatile("mbarrier.init.shared.b64 [%0], %1;" :: "r"(a), "r"(c) : "memory")
#define MBAR_EXPECT_TX(a, b) asm volatile("mbarrier.arrive.expect_tx.shared.b64 _, [%0], %1;" :: "r"(a), "r"(b) : "memory")
#define MBAR_ARRIVE(a) asm volatile("mbarrier.arrive.shared.b64 _, [%0];" :: "r"(a) : "memory")
#define MBAR_WAIT(a, ph) do { \
    uint32_t _m = (a), _p = (ph), _d; \
    asm volatile("{ .reg .pred p; mbarrier.try_wait.parity.acquire.cta.shared::cta.b64 p, [%1], %2; selp.b32 %0,1,0,p; }" \
        : "=r"(_d) : "r"(_m), "r"(_p) : "memory"); \
    if (!_d) { asm volatile("{ .reg .pred P1; W%=: mbarrier.try_wait.parity.acquire.cta.shared::cta.b64 P1, [%0], %1, 0x989680; @P1 bra.uni D%=; bra.uni W%=; D%=: }" \
        :: "r"(_m), "r"(_p) : "memory"); } \
} while (0)

#define BULK_G2S(dst, src, bytes, mbar) \
    asm volatile("cp.async.bulk.shared::cluster.global.mbarrier::complete_tx::bytes [%0], [%1], %2, [%3];" \
        :: "r"(dst), "l"(src), "r"(bytes), "r"(mbar) : "memory")

__device__ __forceinline__ void ldsm4(uint32_t* r, uint32_t addr) {
    asm volatile("ldmatrix.sync.aligned.m8n8.x4.shared.b16 {%0,%1,%2,%3}, [%4];"
        : "=r"(r[0]), "=r"(r[1]), "=r"(r[2]), "=r"(r[3]) : "r"(addr));
}
__device__ __forceinline__ void mma_bf16(float* c, const uint32_t* a, const uint32_t* b) {
    asm volatile("mma.sync.aligned.m16n8k16.row.col.f32.bf16.bf16.f32 "
        "{%0,%1,%2,%3}, {%4,%5,%6,%7}, {%8,%9}, {%0,%1,%2,%3};"
        : "+f"(c[0]), "+f"(c[1]), "+f"(c[2]), "+f"(c[3])
        : "r"(a[0]), "r"(a[1]), "r"(a[2]), "r"(a[3]), "r"(b[0]), "r"(b[1]));
}

__device__ __forceinline__ int img_elem(int r, int c) {    // 128-col bf16 rows
    return r * 128 + (((c >> 3) ^ (r & 7)) << 3) + (c & 7);
}
__device__ __forceinline__ int img64(int r, int c) {       // 64-col bf16 rows
    return r * 64 + (((c >> 3) ^ (r & 7)) << 3) + (c & 7);
}
__device__ __forceinline__ uint32_t pack_bf2(float a, float b) {
    __nv_bfloat162 t = __floats2bfloat162_rn(a, b);
    return *(uint32_t*)&t;
}

// Grid-wide barrier (all NCTA CTAs co-resident)
__device__ __forceinline__ void grid_barrier(int tid) {
    __threadfence();
    asm volatile("fence.proxy.async;" ::: "memory");
    __syncthreads();
    if (tid == 0) {
        unsigned gen0;
        asm volatile("ld.acquire.gpu.u32 %0, [%1];" : "=r"(gen0) : "l"(&g_bar_gen));
        if (atomicAdd(&g_bar_count, 1u) == NCTA - 1) {
            g_bar_count = 0;
            asm volatile("st.release.gpu.u32 [%0], %1;" :: "l"(&g_bar_gen), "r"(gen0 + 1) : "memory");
        } else {
            unsigned g;
            do {
                __nanosleep(32);
                asm volatile("ld.acquire.gpu.u32 %0, [%1];" : "=r"(g) : "l"(&g_bar_gen));
            } while (g == gen0);
        }
    }
    __syncthreads();
}

// ---------------------------------------------------------------------------
// Weight combine
// ---------------------------------------------------------------------------
__device__ __forceinline__ float combineW(const float* Wih, const float* Whh, int g, int j, int k) {
    if (g == 0) return Wih[j*HH + k]          + Whh[j*HH + k];
    if (g == 1) return Wih[(HH + j)*HH + k]   + Whh[(HH + j)*HH + k];
    if (g == 2) return Wih[(2*HH + j)*HH + k];
    return             Whh[(2*HH + j)*HH + k];
}
__device__ __forceinline__ float combineW0(const float* Wih, const float* Whh, int g, int j, int k) {
    if (k < HH) {
        if (g == 0) return Wih[j*HH + k];
        if (g == 1) return Wih[(HH + j)*HH + k];
        if (g == 2) return Wih[(2*HH + j)*HH + k];
        return 0.0f;
    } else {
        int kk = k - HH;
        if (g == 0) return Whh[j*HH + kk];
        if (g == 1) return Whh[(HH + j)*HH + kk];
        if (g == 2) return 0.0f;
        return Whh[(2*HH + j)*HH + kk];
    }
}

// Merged W prep: part 1 = steady (new 64-col layout), part 2 = step-1 (old 128-col)
#define NW1 (NCTA * 16 * 2 * 2048)
__global__ void k_prep_w(const float* __restrict__ Wih, const float* __restrict__ Whh) {
    size_t idx = (size_t)blockIdx.x * blockDim.x + threadIdx.x;
    if (idx < (size_t)NW1) {
        int e  = idx & 2047;
        int h  = (idx >> 11) & 1;
        int kc = (idx >> 12) & 15;
        int n  = (int)(idx >> 16);
        int r = e >> 6, c = e & 63;
        int R = n*32 + r, j = R >> 2, g = R & 3;
        float w = combineW(Wih, Whh, g, j, kc*64 + c);
        __nv_bfloat16 hi = __float2bfloat16_rn(w);
        __nv_bfloat16 v = h ? __float2bfloat16_rn(w - __bfloat162float(hi)) : hi;
        g_Wimg[((size_t)((n*16 + kc)*2 + h)) * 2048 + img64(r, c)] = v;
        return;
    }
    idx -= NW1;
    if (idx >= (size_t)NCTA * 16 * 2 * CH_W_ELEM) return;
    int e  = idx & (CH_W_ELEM - 1);
    int h  = (idx >> 12) & 1;
    int kc = (idx >> 13) & 15;
    int n  = (int)(idx >> 17);
    int r = e >> 7, c = e & 127;
    int R = n*32 + r, j = R >> 2, g = R & 3;
    float w = combineW0(Wih, Whh, g, j, kc*128 + c);
    __nv_bfloat16 hi = __float2bfloat16_rn(w);
    __nv_bfloat16 v = h ? __float2bfloat16_rn(w - __bfloat162float(hi)) : hi;
    g_Wimg0[(((size_t)n*16 + kc)*2 + h) * CH_W_ELEM + img_elem(r, c)] = v;
}

// Merged A0 image + biases + xs[:,0,:] + barrier reset
__global__ void k_prep_a0misc(const float* __restrict__ x0, const float* __restrict__ h0,
                              const float* __restrict__ bih, const float* __restrict__ bhh,
                              float* __restrict__ xs) {
    int idx = blockIdx.x * blockDim.x + threadIdx.x;
    if (idx == 0) { g_bar_count = 0; g_bar_gen = 0; }
    if (idx < NG) {
        int g = idx & 3, j = idx >> 2;
        float v;
        if      (g == 0) v = bih[j]        + bhh[j];
        else if (g == 1) v = bih[HH + j]   + bhh[HH + j];
        else if (g == 2) v = bih[2*HH + j];
        else             v = bhh[2*HH + j];
        g_bci[idx] = v;
    }
    if (idx < BB * HH) {
        int b = idx >> 10, j = idx & (HH - 1);
        xs[b * (TT*HH) + j] = x0[idx];
    }
    if (idx < 16 * 2 * CH_A_ELEM) {
        int e  = idx & (CH_A_ELEM - 1);
        int h  = (idx >> 14) & 1;
        int kc = idx >> 15;
        int m = e >> 7, c = e & 127;
        int k = kc*128 + c;
        float s = (k < HH) ? x0[m*HH + k] : h0[m*HH + (k - HH)];
        __nv_bfloat16 hi = __float2bfloat16_rn(s);
        __nv_bfloat16 v = h ? __float2bfloat16_rn(s - __bfloat162float(hi)) : hi;
        g_A0img[(kc*2 + h) * CH_A_ELEM + img_elem(m, c)] = v;
    }
}

__global__ void k_final(float* __restrict__ outbase) {
    int idx = blockIdx.x * blockDim.x + threadIdx.x;
    if (idx >= BB * HH) return;
    int b = idx >> 10, j = idx & (HH - 1);
    outbase[(size_t)BB * TT * HH + idx] = outbase[b * (TT*HH) + (TT - 1) * HH + j];
}

// ---------------------------------------------------------------------------
// Step-1 kernel (K=2048, streamed 128-col layout), writes xs[:,1,:] + A image.
// ---------------------------------------------------------------------------
__global__ void __launch_bounds__(288, 1)
gru_step1_full(const __nv_bfloat16* __restrict__ Aimg,
               const __nv_bfloat16* __restrict__ Wimg,
               const float* __restrict__ h0,
               float* __restrict__ xs_out,
               __nv_bfloat16* __restrict__ Aout)
{
    constexpr int NC = 16;
    extern __shared__ __align__(128) char smem[];
    const uint32_t sb = smem_u32(smem);
    const int tid = threadIdx.x, wid = tid >> 5, lane = tid & 31;
    const int n = blockIdx.x;

    const uint32_t bar_full0  = sb + 8;
    const uint32_t bar_empty0 = sb + 24;

    if (tid == 0) {
        MBAR_INIT(bar_full0,      1); MBAR_INIT(bar_full0 + 8,  1);
        MBAR_INIT(bar_empty0,     8); MBAR_INIT(bar_empty0 + 8, 8);
    }
    __syncthreads();

    float acc[2][2][4];
#pragma unroll
    for (int mi = 0; mi < 2; mi++)
#pragma unroll
        for (int ni = 0; ni < 2; ni++)
#pragma unroll
            for (int q = 0; q < 4; q++) acc[mi][ni][q] = 0.0f;

    if (wid == 8) {
        if (lane == 0) {
            for (int c = 0; c < NC; c++) {
                int s = c & 1, u = c >> 1;
                if (u > 0) MBAR_WAIT(bar_empty0 + s*8, (u - 1) & 1);
                MBAR_EXPECT_TX(bar_full0 + s*8, 81920u);
                BULK_G2S(sb + SM_A_OFF + s*65536,
                         Aimg + (size_t)c * (2*CH_A_ELEM), 65536u, bar_full0 + s*8);
                BULK_G2S(sb + SM_W_OFF + s*16384,
                         Wimg + ((size_t)n * NC + c) * (2*CH_W_ELEM), 16384u, bar_full0 + s*8);
            }
        }
    } else {
        const int wm = wid & 3, wn = wid >> 2;
        const int ra  = wm*32 + (lane & 15);
        const int ha  = lane >> 4;
        const int rw  = wn*16 + ((lane >> 4) << 3) + (lane & 7);
        const int hw  = (lane >> 3) & 1;
        const uint32_t a_row0 = (uint32_t)(ra * 256);
        const uint32_t a_row1 = (uint32_t)((ra + 16) * 256);
        const int a_sw = ra & 7;
        const uint32_t w_row = (uint32_t)(rw * 256);
        const int w_sw = rw & 7;

        for (int c = 0; c < NC; c++) {
            int s = c & 1, u = c >> 1;
            MBAR_WAIT(bar_full0 + s*8, u & 1);
            const uint32_t sA = sb + SM_A_OFF + s*65536;
            const uint32_t sW = sb + SM_W_OFF + s*16384;
#pragma unroll
            for (int kk = 0; kk < 8; kk++) {
                const uint32_t ua = (uint32_t)(((kk*2 + ha) ^ a_sw) << 4);
                const uint32_t uw = (uint32_t)(((kk*2 + hw) ^ w_sw) << 4);
                uint32_t ahi[2][4], alo[2][4], wh[4], wl[4];
                ldsm4(ahi[0], sA + a_row0 + ua);
                ldsm4(ahi[1], sA + a_row1 + ua);
                ldsm4(alo[0], sA + 32768 + a_row0 + ua);
                ldsm4(alo[1], sA + 32768 + a_row1 + ua);
                ldsm4(wh, sW + w_row + uw);
                ldsm4(wl, sW + 8192 + w_row + uw);
#pragma unroll
                for (int mi = 0; mi < 2; mi++)
#pragma unroll
                    for (int ni = 0; ni < 2; ni++) {
                        mma_bf16(acc[mi][ni], ahi[mi], &wh[ni*2]);
                        mma_bf16(acc[mi][ni], alo[mi], &wh[ni*2]);
                        mma_bf16(acc[mi][ni], ahi[mi], &wl[ni*2]);
                    }
            }
            __syncwarp();
            if (lane == 0) MBAR_ARRIVE(bar_empty0 + s*8);
        }
    }

    __syncthreads();
    float* Dsm = (float*)(smem + SM_A_OFF);
    if (wid < 8) {
        const int wm = wid & 3, wn = wid >> 2;
#pragma unroll
        for (int mi = 0; mi < 2; mi++)
#pragma unroll
            for (int ni = 0; ni < 2; ni++) {
                int row = wm*32 + mi*16 + (lane >> 2);
                int col = wn*16 + ni*8 + (lane & 3)*2;
                Dsm[row*36 + col]       = acc[mi][ni][0];
                Dsm[row*36 + col + 1]   = acc[mi][ni][1];
                Dsm[(row+8)*36 + col]   = acc[mi][ni][2];
                Dsm[(row+8)*36 + col+1] = acc[mi][ni][3];
            }
    }
    __syncthreads();

    if (tid < 256) {
        const int m  = tid & 127;
        const int jj0 = (tid >> 7) * 4;
        const float4 hp4 = *(const float4*)(h0 + (size_t)m * HH + n*8 + jj0);
        const float hps[4] = { hp4.x, hp4.y, hp4.z, hp4.w };
        float hv[4], lov[4];
#pragma unroll
        for (int q = 0; q < 4; q++) {
            const int jj = jj0 + q;
            const float4 b4 = *(const float4*)(g_bci + n*32 + jj*4);
            float rr = Dsm[m*36 + jj*4 + 0] + b4.x;
            float zz = Dsm[m*36 + jj*4 + 1] + b4.y;
            float ni_ = Dsm[m*36 + jj*4 + 2] + b4.z;
            float nh = Dsm[m*36 + jj*4 + 3] + b4.w;
            float r = 1.0f / (1.0f + expf(-rr));
            float z = 1.0f / (1.0f + expf(-zz));
            float nn = tanhf(fmaf(r, nh, ni_));
            float h = fmaf(z, hps[q] - nn, nn);
            hv[q] = h;
            lov[q] = h - __bfloat162float(__float2bfloat16_rn(h));
        }
        *(float4*)(xs_out + (size_t)m * (TT*HH) + n*8 + jj0) =
            make_float4(hv[0], hv[1], hv[2], hv[3]);
        uint32_t base = (uint32_t)((n >> 3) * 16384 + m*64 + (((n & 7) ^ (m & 7)) << 3) + jj0);
        *(uint2*)(Aout + base)        = make_uint2(pack_bf2(hv[0], hv[1]), pack_bf2(hv[2], hv[3]));
        *(uint2*)(Aout + base + 8192) = make_uint2(pack_bf2(lov[0], lov[1]), pack_bf2(lov[2], lov[3]));
    }
}

// ---------------------------------------------------------------------------
// Persistent kernel: steps 2..511. 16 MMA warps (kk-split) + 1 producer.
// Split accumulators (acc_a: hi·wh, acc_x: lo·wh + hi·wl) to shorten chains.
// ---------------------------------------------------------------------------
__global__ void __launch_bounds__(THREADS_P, 1)
gru_persist(const __nv_bfloat16* __restrict__ Wimg,
            float* __restrict__ xs,
            __nv_bfloat16* __restrict__ aimgA,
            __nv_bfloat16* __restrict__ aimgB)
{
    extern __shared__ __align__(128) char smem[];
    const uint32_t sb = smem_u32(smem);
    const int tid = threadIdx.x, wid = tid >> 5, lane = tid & 31;
    const int n = blockIdx.x;

    const uint32_t wbar   = sb + 8;
    const uint32_t fullb  = sb + 16;   // 3 x 8B
    const uint32_t emptyb = sb + 40;   // 3 x 8B
    const uint32_t sA = sb + P_SA;
    const uint32_t sW = sb + P_SW;

    if (tid == 0) {
        MBAR_INIT(wbar, 1);
        for (int s = 0; s < 3; s++) {
            MBAR_INIT(fullb  + s*8, 1);
            MBAR_INIT(emptyb + s*8, 16);
        }
        for (int s = 0; s < 3; s++)
            for (int k = 0; k < 16; k++) MBAR_ARRIVE(emptyb + s*8);   // pre-complete phase 0
    }
    __syncthreads();

    // Resident W tile (128KB), loaded once
    if (tid == 0) {
        MBAR_EXPECT_TX(wbar, 131072u);
        BULK_G2S(sW, Wimg + (size_t)n * 65536, 131072u, wbar);
    }
    MBAR_WAIT(wbar, 0);
    __syncthreads();

    // warp roles: wid 0..15 MMA (sub-tile = wid&7, k-group = wid>>3), wid 16 producer
    const int sub = wid & 7, kg = wid >> 3;
    const int wm = sub & 3, wn = sub >> 2;
    const int ra = wm*32 + (lane & 15);
    const int ha = lane >> 4;
    const int rw = wn*16 + ((lane >> 4) << 3) + (lane & 7);
    const int hw = (lane >> 3) & 1;
    const uint32_t aoff0 = (uint32_t)(ra * 128);
    const uint32_t aoff1 = (uint32_t)((ra + 16) * 128);
    const int a_sw = ra & 7;
    const uint32_t woff = (uint32_t)(rw * 128);
    const int w_sw = rw & 7;

    // Epilogue identity + register-resident h (warps 0-7 only)
    const int m = tid & 127, jj0 = ((tid >> 7) & 1) * 4;
    float hreg[4];
    float4 bj[4];
    if (tid < 256) {
        float4 h4 = *(const float4*)(xs + (size_t)m * (TT*HH) + HH + n*8 + jj0);
        hreg[0] = h4.x; hreg[1] = h4.y; hreg[2] = h4.z; hreg[3] = h4.w;
#pragma unroll
        for (int q = 0; q < 4; q++) bj[q] = *(const float4*)(g_bci + n*32 + (jj0 + q)*4);
    }

    float* D0 = (float*)(smem + P_SA);           // reuses A stages (idle at D-exchange)
    float* D1 = D0 + 128*36;

    int p_stage = 0, p_phase = 0;
    int c_stage = 0, c_phase = 0;

    for (int t = 2; t < TT; t++) {
        const __nv_bfloat16* Ain  = (t & 1) ? aimgB : aimgA;
        __nv_bfloat16*       Aout = (t & 1) ? aimgA : aimgB;

        float acc_a[2][2][4], acc_x[2][2][4];
#pragma unroll
        for (int mi = 0; mi < 2; mi++)
#pragma unroll
            for (int ni = 0; ni < 2; ni++)
#pragma unroll
                for (int q = 0; q < 4; q++) { acc_a[mi][ni][q] = 0.0f; acc_x[mi][ni][q] = 0.0f; }

        if (wid == 16) {
            if (lane == 0) {
                for (int c = 0; c < 16; c++) {
                    int cr = (c + n) & 15;
                    MBAR_WAIT(emptyb + p_stage*8, p_phase);
                    MBAR_EXPECT_TX(fullb + p_stage*8, 32768u);
                    BULK_G2S(sA + p_stage*32768, Ain + (size_t)cr * 16384, 32768u, fullb + p_stage*8);
                    if (++p_stage == 3) { p_stage = 0; p_phase ^= 1; }
                }
            }
        } else {
            for (int c = 0; c < 16; c++) {
                int cr = (c + n) & 15;
                MBAR_WAIT(fullb + c_stage*8, c_phase);
                const uint32_t sAc = sA + c_stage*32768;
                const uint32_t sWc = sW + cr*8192;
#pragma unroll
                for (int kkl = 0; kkl < 2; kkl++) {
                    const int kk = kg*2 + kkl;
                    const uint32_t ua = (uint32_t)(((kk*2 + ha) ^ a_sw) << 4);
                    const uint32_t uw = (uint32_t)(((kk*2 + hw) ^ w_sw) << 4);
                    uint32_t ahi0[4], ahi1[4], alo0[4], alo1[4], wh[4], wl[4];
                    ldsm4(ahi0, sAc + aoff0 + ua);
                    ldsm4(ahi1, sAc + aoff1 + ua);
                    ldsm4(alo0, sAc + 16384 + aoff0 + ua);
                    ldsm4(alo1, sAc + 16384 + aoff1 + ua);
                    ldsm4(wh, sWc + woff + uw);
                    ldsm4(wl, sWc + 4096 + woff + uw);
#pragma unroll
                    for (int ni = 0; ni < 2; ni++) {
                        mma_bf16(acc_a[0][ni], ahi0, &wh[ni*2]);
                        mma_bf16(acc_a[1][ni], ahi1, &wh[ni*2]);
                        mma_bf16(acc_x[0][ni], alo0, &wh[ni*2]);
                        mma_bf16(acc_x[1][ni], alo1, &wh[ni*2]);
                        mma_bf16(acc_x[0][ni], ahi0, &wl[ni*2]);
                        mma_bf16(acc_x[1][ni], ahi1, &wl[ni*2]);
                    }
                }
                __syncwarp();
                if (lane == 0) MBAR_ARRIVE(emptyb + c_stage*8);
                if (++c_stage == 3) { c_stage = 0; c_phase ^= 1; }
            }
        }

        __syncthreads();   // all chunks consumed; stage smem idle -> D exchange

        if (wid < 16) {
            float* Dw = kg ? D1 : D0;
#pragma unroll
            for (int mi = 0; mi < 2; mi++)
#pragma unroll
                for (int ni = 0; ni < 2; ni++) {
                    int row = wm*32 + mi*16 + (lane >> 2);
                    int col = wn*16 + ni*8 + (lane & 3)*2;
                    Dw[row*36 + col]       = acc_a[mi][ni][0] + acc_x[mi][ni][0];
                    Dw[row*36 + col + 1]   = acc_a[mi][ni][1] + acc_x[mi][ni][1];
                    Dw[(row+8)*36 + col]   = acc_a[mi][ni][2] + acc_x[mi][ni][2];
                    Dw[(row+8)*36 + col+1] = acc_a[mi][ni][3] + acc_x[mi][ni][3];
                }
        }
        __syncthreads();

        if (tid < 256) {
            float hv[4], lov[4];
#pragma unroll
            for (int q = 0; q < 4; q++) {
                const int jj = jj0 + q;
                float rr = D0[m*36 + jj*4 + 0] + D1[m*36 + jj*4 + 0] + bj[q].x;
                float zz = D0[m*36 + jj*4 + 1] + D1[m*36 + jj*4 + 1] + bj[q].y;
                float ni_ = D0[m*36 + jj*4 + 2] + D1[m*36 + jj*4 + 2] + bj[q].z;
                float nh = D0[m*36 + jj*4 + 3] + D1[m*36 + jj*4 + 3] + bj[q].w;
                float r = 1.0f / (1.0f + expf(-rr));
                float z = 1.0f / (1.0f + expf(-zz));
                float nn = tanhf(fmaf(r, nh, ni_));
                float h = fmaf(z, hreg[q] - nn, nn);
                hv[q] = h; hreg[q] = h;
                lov[q] = h - __bfloat162float(__float2bfloat16_rn(h));
            }
            *(float4*)(xs + (size_t)m * (TT*HH) + (size_t)t * HH + n*8 + jj0) =
                make_float4(hv[0], hv[1], hv[2], hv[3]);
            uint32_t base = (uint32_t)((n >> 3) * 16384 + m*64 + (((n & 7) ^ (m & 7)) << 3) + jj0);
            *(uint2*)(Aout + base)        = make_uint2(pack_bf2(hv[0], hv[1]), pack_bf2(hv[2], hv[3]));
            *(uint2*)(Aout + base + 8192) = make_uint2(pack_bf2(lov[0], lov[1]), pack_bf2(lov[2], lov[3]));
        }

        grid_barrier(tid);
    }
}

// ---------------------------------------------------------------------------
// Host launch: prep_w, prep_a0misc, step1, persist (4th = ncu slot), final.
// ---------------------------------------------------------------------------
extern "C" void kernel_launch(void* const* d_in, const int* in_sizes, int n_in,
                              void* d_out, int out_size)
{
    int ix0 = -1, ih0 = -1, iwih = -1, iwhh = -1, ibih = -1, ibhh = -1;
    for (int i = 0; i < n_in; i++) {
        int s = in_sizes[i];
        if      (s == BB * HH)     { if (ix0  < 0) ix0  = i; else if (ih0  < 0) ih0  = i; }
        else if (s == 3 * HH * HH) { if (iwih < 0) iwih = i; else if (iwhh < 0) iwhh = i; }
        else if (s == 3 * HH)      { if (ibih < 0) ibih = i; else if (ibhh < 0) ibhh = i; }
    }
    const float* x0  = (const float*)d_in[ix0];
    const float* h0  = (const float*)d_in[ih0];
    const float* Wih = (const float*)d_in[iwih];
    const float* Whh = (const float*)d_in[iwhh];
    const float* bih = (const float*)d_in[ibih];
    const float* bhh = (const float*)d_in[ibhh];
    float* xs = (float*)d_out;

    cudaFuncSetAttribute(gru_step1_full, cudaFuncAttributeMaxDynamicSharedMemorySize, SMEM_TOTAL1);
    cudaFuncSetAttribute(gru_persist,    cudaFuncAttributeMaxDynamicSharedMemorySize, SMEM_TOTALP);

    // Prep (2 launches)
    {
        size_t nw = (size_t)NW1 + (size_t)NCTA * 16 * 2 * CH_W_ELEM;
        k_prep_w<<<(unsigned)((nw + 255) / 256), 256>>>(Wih, Whh);
        int na = 16 * 2 * CH_A_ELEM;
        k_prep_a0misc<<<(na + 255) / 256, 256>>>(x0, h0, bih, bhh, xs);
    }

    __nv_bfloat16 *aimg0, *a0img, *wimg, *wimg0;
    cudaGetSymbolAddress((void**)&aimg0, g_Aimg);
    cudaGetSymbolAddress((void**)&a0img, g_A0img);
    cudaGetSymbolAddress((void**)&wimg,  g_Wimg);
    cudaGetSymbolAddress((void**)&wimg0, g_Wimg0);
    __nv_bfloat16* aimgA = aimg0;
    __nv_bfloat16* aimgB = aimg0 + 16 * 16384;

    // Step t=1 (K=2048): writes xs[:,1,:] + A image A
    gru_step1_full<<<NCTA, 288, SMEM_TOTAL1>>>(a0img, wimg0, h0, xs + 1 * HH, aimgA);

    // Steps t=2..511 (4th launch -> gets profiled)
    gru_persist<<<NCTA, THREADS_P, SMEM_TOTALP>>>(wimg, xs, aimgA, aimgB);

    k_final<<<(BB * HH + 255) / 256, 256>>>(xs);
}